// round 9
// baseline (speedup 1.0000x reference)
#include <cuda_runtime.h>

// Problem constants
#define B_TOT  2
#define E_TOT  2048
#define N1_TOT 96
#define K_TOT  32
#define CIN    64
#define CB     32
#define COUT   64
#define F_TOT  160          // 2*CIN + CB
#define NPAIR  80           // F_TOT/2
#define WCNT   (F_TOT*COUT) // 10240 floats
#define NEG_SLOPE 0.01f

#define EPC     32          // edges per CTA
#define GRID_M  128         // 4096 / 32
#define VSTRIDE 34          // u64 stride per f-pair row of vP (pad)

// fma on packed f32x2 (feature pairs)
#define FMA2(acc, v, wgt) \
    asm("fma.rn.f32x2 %0, %1, %2, %0;" : "+l"(acc) : "l"(v), "l"(wgt))

// Wbar = mean_g W_eq[g] in f-pair u64 layout:
//   float index i = kp*128 + 2*o + j  ->  Wbar[f = 2*kp + j][o]
// so u64 WP[kp*64 + o] = {W[2kp][o], W[2kp+1][o]}
__device__ float g_WP[WCNT];

// ---------------------------------------------------------------------------
// Prep: Wbar into f-pair layout + zero d_out. PDL completion fires early so
// the main kernel's (independent) v-gather overlaps this.
// ---------------------------------------------------------------------------
__global__ void prep_kernel(const float* __restrict__ W_eq, float* __restrict__ out) {
#if __CUDA_ARCH__ >= 900
    cudaTriggerProgrammaticLaunchCompletion();
#endif
    int i = blockIdx.x * blockDim.x + threadIdx.x;
    if (i < WCNT) {
        const int kp = i >> 7, r = i & 127, o = r >> 1, j = r & 1;
        const int idx = (2 * kp + j) * COUT + o;
        float s = W_eq[idx] + W_eq[WCNT + idx] + W_eq[2 * WCNT + idx] + W_eq[3 * WCNT + idx];
        g_WP[i] = 0.25f * s;
    }
    if (i < B_TOT * K_TOT * COUT) out[i] = 0.0f;
}

// ---------------------------------------------------------------------------
// Main: 128 CTAs x 256 threads. CTA owns 32 edges x 64 outputs.
// Warp w = output octet (outs 8w..8w+7). Thread lane = ot*8 + et:
//   et in [0,8): edge quartet 4et..4et+3;  ot in [0,4): output pair.
// Per f-pair step: 2 LDS.128 (v, shared across ot) + 1 LDS.128 (W, shared
// across et) + 8 FMA2 => 512 MACs per warp-step.
// ---------------------------------------------------------------------------
__global__ void __launch_bounds__(256, 1) main_kernel(
    const float* __restrict__ sites1,
    const float* __restrict__ sites2,
    const float* __restrict__ bonds,
    const float* __restrict__ b_eq,
    const float* __restrict__ W_att,
    const float* __restrict__ b_att,
    const int*   __restrict__ idx1,
    const int*   __restrict__ idx2,
    float* __restrict__ out)
{
    extern __shared__ char smem_raw[];
    unsigned long long* WPs = (unsigned long long*)smem_raw;        // 5120 u64 (40960 B)
    float2* vP  = (float2*)(WPs + NPAIR * 64);                      // 80*VSTRIDE u64 (21760 B)
    float*  psum = (float*)(vP + NPAIR * VSTRIDE);                  // 8*32 floats (1024 B)

    const int tid  = threadIdx.x;
    const int lane = tid & 31;
    const int w    = tid >> 5;
    const int et   = lane & 7;
    const int ot   = lane >> 3;
    const int opi  = w * 4 + ot;            // output pair index: outs {2opi, 2opi+1}

    // ---- Per-lane edge metadata (edge = lane within this CTA) ----
    const int ei = blockIdx.x * EPC + lane;     // 0..4095
    const int b  = ei >> 11;
    const int e  = ei & (E_TOT - 1);
    const int i1 = idx1[e];
    const int i2 = idx2[e];
    const int rowoff = (b * K_TOT + i2) * COUT;

    // ---- Phase A: gather v into transposed f-pair layout (PDL-independent).
    // Warp w gathers edges 4w..4w+3. Lane l stages feature pair {2l, 2l+1}.
    #pragma unroll
    for (int jj = 0; jj < 4; jj++) {
        const int le  = 4 * w + jj;
        const int eb  = __shfl_sync(0xffffffffu, b,  le);
        const int ee  = __shfl_sync(0xffffffffu, e,  le);
        const int ei1 = __shfl_sync(0xffffffffu, i1, le);
        const int ei2 = __shfl_sync(0xffffffffu, i2, le);
        const float2* s1r = (const float2*)(sites1 + (eb * N1_TOT + ei1) * CIN);
        const float2* s2r = (const float2*)(sites2 + (eb * K_TOT  + ei2) * CIN);
        const float2* bdr = (const float2*)(bonds  + (eb * E_TOT  + ee ) * CB);
        vP[lane * VSTRIDE + le]        = s1r[lane];   // kp = lane       (f 0..63)
        vP[(32 + lane) * VSTRIDE + le] = s2r[lane];   // kp = 32+lane    (f 64..127)
        if (lane < 16)
            vP[(64 + lane) * VSTRIDE + le] = bdr[lane]; // kp = 64+lane  (f 128..159)
    }

    // ---- Wait for prep (WP ready, out zeroed) ----
#if __CUDA_ARCH__ >= 900
    cudaGridDependencySynchronize();
#endif

    // ---- Phase B: stage WP (f-pair layout), straight float4 copy ----
    {
        const float4* src = (const float4*)g_WP;
        float4*       dst = (float4*)WPs;
        #pragma unroll
        for (int i = 0; i < 10; i++) dst[i * 256 + tid] = src[i * 256 + tid];
    }
    __syncthreads();

    // ---- Phase C: outer-product loop over 80 f-pairs ----
    const ulonglong2* Wq = (const ulonglong2*)WPs;  // [kp*32 + opi] = {WP[2opi], WP[2opi+1]}
    const ulonglong2* Vq = (const ulonglong2*)vP;   // [kp*17 + 2et+h] = v pairs, 2 edges each

    unsigned long long a00 = 0ull, a01 = 0ull, a10 = 0ull, a11 = 0ull;
    unsigned long long a20 = 0ull, a21 = 0ull, a30 = 0ull, a31 = 0ull;

    #pragma unroll 5
    for (int kp = 0; kp < NPAIR; kp++) {
        const ulonglong2 wp = Wq[kp * 32 + opi];           // {w(o0), w(o1)}
        const ulonglong2 va = Vq[kp * 17 + 2 * et];        // {v(e0), v(e1)}
        const ulonglong2 vb = Vq[kp * 17 + 2 * et + 1];    // {v(e2), v(e3)}
        FMA2(a00, va.x, wp.x);  FMA2(a01, va.x, wp.y);
        FMA2(a10, va.y, wp.x);  FMA2(a11, va.y, wp.y);
        FMA2(a20, vb.x, wp.x);  FMA2(a21, vb.x, wp.y);
        FMA2(a30, vb.y, wp.x);  FMA2(a31, vb.y, wp.y);
    }

    // ---- Phase D: epilogue ----
    const int o0 = 2 * opi, o1 = o0 + 1;
    const float be0 = b_eq[o0],  be1 = b_eq[o1];
    const float wa0 = W_att[o0], wa1 = W_att[o1];
    const float ba  = b_att[0];

    unsigned long long A0[4] = {a00, a10, a20, a30};
    unsigned long long A1[4] = {a01, a11, a21, a31};
    float y0[4], y1[4], p[4];

    #pragma unroll
    for (int j = 0; j < 4; j++) {
        float t0 = __uint_as_float((unsigned)(A0[j] & 0xffffffffull))
                 + __uint_as_float((unsigned)(A0[j] >> 32)) + be0;
        float t1 = __uint_as_float((unsigned)(A1[j] & 0xffffffffull))
                 + __uint_as_float((unsigned)(A1[j] >> 32)) + be1;
        t0 = (t0 > 0.0f) ? t0 : NEG_SLOPE * t0;
        t1 = (t1 > 0.0f) ? t1 : NEG_SLOPE * t1;
        y0[j] = t0; y1[j] = t1;
        p[j] = t0 * wa0 + t1 * wa1;
    }

    // Reduce attention partials over the 4 ot lanes (xor bits 3,4).
    #pragma unroll
    for (int j = 0; j < 4; j++) {
        p[j] += __shfl_xor_sync(0xffffffffu, p[j], 8);
        p[j] += __shfl_xor_sync(0xffffffffu, p[j], 16);
    }
    if (ot == 0) {
        #pragma unroll
        for (int j = 0; j < 4; j++) psum[w * 32 + 4 * et + j] = p[j];
    }
    __syncthreads();

    // Every warp computes att for edge = lane (redundant, bar-free afterwards).
    float P = ba;
    #pragma unroll
    for (int ww = 0; ww < 8; ww++) P += psum[ww * 32 + lane];
    const float att = 1.0f / (1.0f + __expf(-P));

    // Scatter: thread adds 4 edges x 2 outs.
    #pragma unroll
    for (int j = 0; j < 4; j++) {
        const int le = 4 * et + j;
        const float a  = __shfl_sync(0xffffffffu, att,    le);
        const int   ro = __shfl_sync(0xffffffffu, rowoff, le);
        atomicAdd(out + ro + o0, a * y0[j]);
        atomicAdd(out + ro + o1, a * y1[j]);
    }
}

// ---------------------------------------------------------------------------
extern "C" void kernel_launch(void* const* d_in, const int* in_sizes, int n_in,
                              void* d_out, int out_size)
{
    const float* sites1 = (const float*)d_in[0];
    const float* sites2 = (const float*)d_in[1];
    const float* bonds  = (const float*)d_in[2];
    const float* W_eq   = (const float*)d_in[3];
    const float* b_eq   = (const float*)d_in[4];
    const float* W_att  = (const float*)d_in[5];
    const float* b_att  = (const float*)d_in[6];
    // d_in[7] = idx2_oh (unused — collapsed analytically)
    const int*   idx1   = (const int*)d_in[8];
    const int*   idx2   = (const int*)d_in[9];
    // d_in[10], d_in[11] = perms1/perms2 (unused — permutations cancel)
    float* out = (float*)d_out;

    const int smem_bytes = NPAIR * 64 * 8          // WPs (40960)
                         + NPAIR * VSTRIDE * 8     // vP  (21760)
                         + 8 * 32 * 4;             // psum (1024)
    cudaFuncSetAttribute(main_kernel,
                         cudaFuncAttributeMaxDynamicSharedMemorySize, smem_bytes);

    // prep on stream 0
    {
        cudaLaunchConfig_t cfg = {};
        cfg.gridDim  = dim3(40);
        cfg.blockDim = dim3(256);
        cfg.dynamicSmemBytes = 0;
        cfg.stream = 0;
        cudaLaunchKernelEx(&cfg, prep_kernel, W_eq, out);
    }

    // main on stream 0 with programmatic dependent launch
    {
        cudaLaunchConfig_t cfg = {};
        cfg.gridDim  = dim3(GRID_M);
        cfg.blockDim = dim3(256);
        cfg.dynamicSmemBytes = smem_bytes;
        cfg.stream = 0;
        cudaLaunchAttribute at[1];
        at[0].id = cudaLaunchAttributeProgrammaticStreamSerialization;
        at[0].val.programmaticStreamSerializationAllowed = 1;
        cfg.attrs = at;
        cfg.numAttrs = 1;
        cudaLaunchKernelEx(&cfg, main_kernel, sites1, sites2, bonds,
                           b_eq, W_att, b_att, idx1, idx2, out);
    }
}

// round 10
// speedup vs baseline: 1.3769x; 1.3769x over previous
#include <cuda_runtime.h>

// Problem constants
#define B_TOT  2
#define E_TOT  2048
#define N1_TOT 96
#define K_TOT  32
#define CIN    64
#define CB     32
#define COUT   64
#define F_TOT  160
#define WCNT   (F_TOT*COUT)   // 10240 floats per group
#define NEG_SLOPE 0.01f

#define NPB    16             // bond feature pairs (CB/2)
#define WBOT_CNT (CB*COUT)    // 2048 floats
#define EPW    4
#define WPC    8
#define EPC    (EPW*WPC)      // 32 edges per CTA
#define GRID_M 128            // 4096/32

#define CTOP_ROWS (B_TOT*N1_TOT)  // 192
#define CMID_ROWS (B_TOT*K_TOT)   // 64

// fma on packed f32x2 (feature pairs)
#define FMA2(acc, v, wgt) \
    asm("fma.rn.f32x2 %0, %1, %2, %0;" : "+l"(acc) : "l"(v), "l"(wgt))

// Precomputed partial matvecs (prep outputs):
//   g_ctop[(b*96+n1)*64 + o] = s1[b,n1,:] . Wbar[0:64, o]
//   g_cmid[(b*32+k )*64 + o] = s2[b,k ,:] . Wbar[64:128, o] + b_eq[o]
// W_bot (Wbar rows 128..159) in paired layout for LDS.128:
//   float i = ip*128 + t*4 + slot -> Wbot[f=2*ip+(slot&1)][o=t+32*(slot>>1)], ip<16
__device__ float g_ctop[CTOP_ROWS * COUT];
__device__ float g_cmid[CMID_ROWS * COUT];
__device__ float g_WbotP[WBOT_CNT];

// ---------------------------------------------------------------------------
// Prep: blocks 0..191  -> c_top rows;  192..255 -> c_mid rows (+b_eq);
//       blocks 256..271 -> WbotP + zero d_out.  64 threads per block.
// PDL completion fires at start so main's bonds-gather overlaps.
// ---------------------------------------------------------------------------
__global__ void __launch_bounds__(64) prep_kernel(
    const float* __restrict__ sites1,
    const float* __restrict__ sites2,
    const float* __restrict__ W_eq,
    const float* __restrict__ b_eq,
    float* __restrict__ out)
{
#if __CUDA_ARCH__ >= 900
    cudaTriggerProgrammaticLaunchCompletion();
#endif
    const int r   = blockIdx.x;
    const int tid = threadIdx.x;

    if (r < CTOP_ROWS + CMID_ROWS) {
        __shared__ float s_sh[CIN];
        const bool top = (r < CTOP_ROWS);
        const float* srow = top ? (sites1 + r * CIN)
                                : (sites2 + (r - CTOP_ROWS) * CIN);
        s_sh[tid] = srow[tid];
        __syncthreads();

        const int f0 = top ? 0 : CIN;
        const float* Wb = W_eq + f0 * COUT + tid;
        float acc = 0.0f;
        #pragma unroll 8
        for (int f = 0; f < CIN; f++) {
            const float sv = s_sh[f];
            const float ws = Wb[f * COUT]
                           + Wb[f * COUT + WCNT]
                           + Wb[f * COUT + 2 * WCNT]
                           + Wb[f * COUT + 3 * WCNT];
            acc += sv * ws;
        }
        acc *= 0.25f;
        if (top) g_ctop[r * COUT + tid] = acc;
        else     g_cmid[(r - CTOP_ROWS) * COUT + tid] = acc + b_eq[tid];
    } else {
        // WbotP (2048) + zero out (4096)
        const int base = (r - (CTOP_ROWS + CMID_ROWS)) * 64 + tid;  // 0..1023
        #pragma unroll
        for (int h = 0; h < 2; h++) {
            const int i  = base + h * 1024;        // 0..2047
            const int ip = i >> 7, rr = i & 127, t = rr >> 2, slot = rr & 3;
            const int f  = 128 + 2 * ip + (slot & 1);
            const int o  = t + 32 * (slot >> 1);
            const int idx = f * COUT + o;
            g_WbotP[i] = 0.25f * (W_eq[idx] + W_eq[WCNT + idx]
                                + W_eq[2 * WCNT + idx] + W_eq[3 * WCNT + idx]);
        }
        #pragma unroll
        for (int h = 0; h < 4; h++) out[base + h * 1024] = 0.0f;
    }
}

// ---------------------------------------------------------------------------
// Main: 128 CTAs x 256 threads (8 warps). Warp owns 4 edges.
// Per edge: lat = c_top[b,i1] + c_mid[b,i2](+b_eq) + bonds[b,e].W_bot
// Inner loop: only 16 f-pair iters (bonds features).
// Thread t owns outputs {t, t+32}.
// ---------------------------------------------------------------------------
__global__ void __launch_bounds__(256, 1) main_kernel(
    const float* __restrict__ bonds,
    const float* __restrict__ W_att,
    const float* __restrict__ b_att,
    const int*   __restrict__ idx1,
    const int*   __restrict__ idx2,
    float* __restrict__ out)
{
    __shared__ float Wsh[WBOT_CNT];          // 8192 B
    __shared__ float vsh[EPC * CB];          // 4096 B

    const int tid  = threadIdx.x;
    const int lane = tid & 31;
    const int w    = tid >> 5;

    // ---- Phase A: bonds gather + metadata (independent of prep) ----
    int ctop_off[EPW], cmid_off[EPW], row_off[EPW];
    #pragma unroll
    for (int j = 0; j < EPW; j++) {
        const int le = w * EPW + j;
        const int ei = blockIdx.x * EPC + le;
        const int b  = ei >> 11;
        const int e  = ei & (E_TOT - 1);
        const int i1 = idx1[e];    // broadcast load
        const int i2 = idx2[e];
        ctop_off[j] = (b * N1_TOT + i1) * COUT;
        cmid_off[j] = (b * K_TOT  + i2) * COUT;
        row_off[j]  = (b * K_TOT  + i2) * COUT;
        vsh[le * CB + lane] = bonds[(b * E_TOT + e) * CB + lane];
    }
    const float waT = W_att[lane];
    const float waU = W_att[lane + 32];
    const float ba  = b_att[0];

    // ---- Wait for prep outputs (ctop/cmid/WbotP/out-zero) ----
#if __CUDA_ARCH__ >= 900
    cudaGridDependencySynchronize();
#endif

    // Prefetch c_top / c_mid rows (coalesced, L2)
    float ctT[EPW], ctU[EPW], cmT[EPW], cmU[EPW];
    #pragma unroll
    for (int j = 0; j < EPW; j++) {
        ctT[j] = g_ctop[ctop_off[j] + lane];
        ctU[j] = g_ctop[ctop_off[j] + lane + 32];
        cmT[j] = g_cmid[cmid_off[j] + lane];
        cmU[j] = g_cmid[cmid_off[j] + lane + 32];
    }

    // ---- Phase B: stage WbotP ----
    {
        const float4* src = (const float4*)g_WbotP;
        float4*       dst = (float4*)Wsh;
        #pragma unroll
        for (int i = 0; i < 2; i++) dst[i * 256 + tid] = src[i * 256 + tid];
    }
    __syncthreads();

    // ---- Phase C: 16 f-pair iters x 4 edges ----
    const ulonglong2* Wq = (const ulonglong2*)Wsh;
    const float* vb = vsh + (w * EPW) * CB;

    unsigned long long aT[EPW], aU[EPW];
    #pragma unroll
    for (int j = 0; j < EPW; j++) { aT[j] = 0ull; aU[j] = 0ull; }

    #pragma unroll
    for (int ip = 0; ip < NPB; ip++) {
        const ulonglong2 wq = Wq[ip * 32 + lane];
        #pragma unroll
        for (int j = 0; j < EPW; j++) {
            const unsigned long long vp =
                *(const unsigned long long*)(vb + j * CB + 2 * ip);  // broadcast
            FMA2(aT[j], vp, wq.x);
            FMA2(aU[j], vp, wq.y);
        }
    }

    // ---- Phase D: epilogue ----
    #pragma unroll
    for (int j = 0; j < EPW; j++) {
        float yT = __uint_as_float((unsigned)(aT[j] & 0xffffffffull))
                 + __uint_as_float((unsigned)(aT[j] >> 32))
                 + ctT[j] + cmT[j];
        float yU = __uint_as_float((unsigned)(aU[j] & 0xffffffffull))
                 + __uint_as_float((unsigned)(aU[j] >> 32))
                 + ctU[j] + cmU[j];
        yT = (yT > 0.0f) ? yT : NEG_SLOPE * yT;
        yU = (yU > 0.0f) ? yU : NEG_SLOPE * yU;

        float p = yT * waT + yU * waU;
        #pragma unroll
        for (int s = 16; s > 0; s >>= 1)
            p += __shfl_xor_sync(0xffffffffu, p, s);
        const float att = 1.0f / (1.0f + __expf(-(p + ba)));

        float* dst = out + row_off[j];
        atomicAdd(dst + lane,      att * yT);
        atomicAdd(dst + lane + 32, att * yU);
    }
}

// ---------------------------------------------------------------------------
extern "C" void kernel_launch(void* const* d_in, const int* in_sizes, int n_in,
                              void* d_out, int out_size)
{
    const float* sites1 = (const float*)d_in[0];
    const float* sites2 = (const float*)d_in[1];
    const float* bonds  = (const float*)d_in[2];
    const float* W_eq   = (const float*)d_in[3];
    const float* b_eq   = (const float*)d_in[4];
    const float* W_att  = (const float*)d_in[5];
    const float* b_att  = (const float*)d_in[6];
    // d_in[7] = idx2_oh (unused — collapsed analytically)
    const int*   idx1   = (const int*)d_in[8];
    const int*   idx2   = (const int*)d_in[9];
    // d_in[10], d_in[11] = perms1/perms2 (unused — permutations cancel)
    float* out = (float*)d_out;

    // prep: 192 c_top rows + 64 c_mid rows + 16 misc blocks = 272 blocks
    {
        cudaLaunchConfig_t cfg = {};
        cfg.gridDim  = dim3(CTOP_ROWS + CMID_ROWS + 16);
        cfg.blockDim = dim3(64);
        cfg.stream = 0;
        cudaLaunchKernelEx(&cfg, prep_kernel, sites1, sites2, W_eq, b_eq, out);
    }

    // main with programmatic dependent launch (bonds-gather overlaps prep)
    {
        cudaLaunchConfig_t cfg = {};
        cfg.gridDim  = dim3(GRID_M);
        cfg.blockDim = dim3(256);
        cfg.stream = 0;
        cudaLaunchAttribute at[1];
        at[0].id = cudaLaunchAttributeProgrammaticStreamSerialization;
        at[0].val.programmaticStreamSerializationAllowed = 1;
        cfg.attrs = at;
        cfg.numAttrs = 1;
        cudaLaunchKernelEx(&cfg, main_kernel, bonds, W_att, b_att,
                           idx1, idx2, out);
    }
}

// round 11
// speedup vs baseline: 1.4410x; 1.0466x over previous
#include <cuda_runtime.h>

// Problem constants
#define B_TOT  2
#define E_TOT  2048
#define N1_TOT 96
#define K_TOT  32
#define CIN    64
#define CB     32
#define COUT   64
#define F_TOT  160
#define WCNT   (F_TOT*COUT)   // 10240 floats per group
#define NEG_SLOPE 0.01f

#define NPB    16             // bond feature pairs (CB/2)
#define WBOT_CNT (CB*COUT)    // 2048 floats
#define EPW    4
#define WPC    8
#define EPC    (EPW*WPC)      // 32 edges per CTA
#define GRID_M 128            // 4096/32

#define CTOP_ROWS (B_TOT*N1_TOT)  // 192
#define CMID_ROWS (B_TOT*K_TOT)   // 64

// fma on packed f32x2 (feature pairs)
#define FMA2(acc, v, wgt) \
    asm("fma.rn.f32x2 %0, %1, %2, %0;" : "+l"(acc) : "l"(v), "l"(wgt))

// Precomputed partial matvecs (prep outputs):
//   g_ctop[(b*96+n1)*64 + o] = s1[b,n1,:] . Wbar[0:64, o]
//   g_cmid[(b*32+k )*64 + o] = s2[b,k ,:] . Wbar[64:128, o] + b_eq[o]
// W_bot (Wbar rows 128..159) in paired layout for LDS.128 in main:
//   float i = ip*128 + t*4 + slot -> Wbot[f=2*ip+(slot&1)][o=t+32*(slot>>1)], ip<16
__device__ float g_ctop[CTOP_ROWS * COUT];
__device__ float g_cmid[CMID_ROWS * COUT];
__device__ float g_WbotP[WBOT_CNT];

// ---------------------------------------------------------------------------
// Prep: 64 CTAs x 256 threads. Every CTA stages averaged W[0:128] (top+mid)
// into smem with coalesced float4 loads, then computes 3 c_top rows + 1 c_mid
// row (slot = tid>>6). CTAs 0..15 also emit WbotP and zero d_out.
// PDL completion fires at start so main's bonds-gather overlaps.
// ---------------------------------------------------------------------------
__global__ void __launch_bounds__(256, 1) prep_kernel(
    const float* __restrict__ sites1,
    const float* __restrict__ sites2,
    const float* __restrict__ W_eq,
    const float* __restrict__ b_eq,
    float* __restrict__ out)
{
#if __CUDA_ARCH__ >= 900
    cudaTriggerProgrammaticLaunchCompletion();
#endif
    __shared__ float Wsh[128 * COUT];    // averaged W rows 0..127 (32768 B)
    __shared__ float s_sh[4 * COUT];     // one s row per slot

    const int tid  = threadIdx.x;
    const int c    = blockIdx.x;
    const int slot = tid >> 6;           // 0..3
    const int o    = tid & 63;

    // Stage averaged W[0:128][:] as float4 (2048 positions, 8/thread).
    {
        const float4* g0 = (const float4*)W_eq;
        const float4* g1 = (const float4*)(W_eq + WCNT);
        const float4* g2 = (const float4*)(W_eq + 2 * WCNT);
        const float4* g3 = (const float4*)(W_eq + 3 * WCNT);
        float4* dst = (float4*)Wsh;
        #pragma unroll
        for (int j = 0; j < 8; j++) {
            const int i = tid + j * 256;          // 0..2047
            const float4 a = g0[i], b4 = g1[i], cc = g2[i], d = g3[i];
            float4 r;
            r.x = 0.25f * (a.x + b4.x + cc.x + d.x);
            r.y = 0.25f * (a.y + b4.y + cc.y + d.y);
            r.z = 0.25f * (a.z + b4.z + cc.z + d.z);
            r.w = 0.25f * (a.w + b4.w + cc.w + d.w);
            dst[i] = r;
        }
    }

    // Stage this slot's s row.
    // slots 0..2: c_top row r = 3c+slot (flat sites1 row). slot 3: c_mid row c.
    const int r = (slot < 3) ? (3 * c + slot) : c;
    const float* srow = (slot < 3) ? (sites1 + r * CIN) : (sites2 + r * CIN);
    s_sh[slot * COUT + o] = srow[o];
    __syncthreads();

    // 64-MAC dot per thread.
    const int base_f = (slot < 3) ? 0 : CIN;
    float acc = 0.0f;
    #pragma unroll 16
    for (int f = 0; f < CIN; f++)
        acc += s_sh[slot * COUT + f] * Wsh[(base_f + f) * COUT + o];

    if (slot < 3) g_ctop[r * COUT + o] = acc;
    else          g_cmid[r * COUT + o] = acc + b_eq[o];

    // CTAs 0..15: WbotP (128 elems each) + zero out (256 elems each).
    if (c < 16) {
        if (tid < 128) {
            const int i  = c * 128 + tid;          // 0..2047
            const int ip = i >> 7, rr = i & 127, t = rr >> 2, sl = rr & 3;
            const int f  = 128 + 2 * ip + (sl & 1);
            const int oo = t + 32 * (sl >> 1);
            const int idx = f * COUT + oo;
            g_WbotP[i] = 0.25f * (W_eq[idx] + W_eq[WCNT + idx]
                                + W_eq[2 * WCNT + idx] + W_eq[3 * WCNT + idx]);
        }
        out[c * 256 + tid] = 0.0f;
    }
}

// ---------------------------------------------------------------------------
// Main: 128 CTAs x 256 threads (8 warps). Warp owns 4 edges.
// Per edge: lat = c_top[b,i1] + c_mid[b,i2](+b_eq) + bonds[b,e].W_bot
// Inner loop: only 16 f-pair iters (bonds features).
// Thread t owns outputs {t, t+32}.
// ---------------------------------------------------------------------------
__global__ void __launch_bounds__(256, 1) main_kernel(
    const float* __restrict__ bonds,
    const float* __restrict__ W_att,
    const float* __restrict__ b_att,
    const int*   __restrict__ idx1,
    const int*   __restrict__ idx2,
    float* __restrict__ out)
{
    __shared__ float Wsh[WBOT_CNT];          // 8192 B
    __shared__ float vsh[EPC * CB];          // 4096 B

    const int tid  = threadIdx.x;
    const int lane = tid & 31;
    const int w    = tid >> 5;

    // ---- Phase A: bonds gather + metadata (independent of prep) ----
    int ctop_off[EPW], cmid_off[EPW];
    #pragma unroll
    for (int j = 0; j < EPW; j++) {
        const int le = w * EPW + j;
        const int ei = blockIdx.x * EPC + le;
        const int b  = ei >> 11;
        const int e  = ei & (E_TOT - 1);
        const int i1 = idx1[e];    // broadcast load
        const int i2 = idx2[e];
        ctop_off[j] = (b * N1_TOT + i1) * COUT;
        cmid_off[j] = (b * K_TOT  + i2) * COUT;
        vsh[le * CB + lane] = bonds[(b * E_TOT + e) * CB + lane];
    }
    const float waT = W_att[lane];
    const float waU = W_att[lane + 32];
    const float ba  = b_att[0];

    // ---- Wait for prep outputs (ctop/cmid/WbotP/out-zero) ----
#if __CUDA_ARCH__ >= 900
    cudaGridDependencySynchronize();
#endif

    // Prefetch c_top / c_mid rows (coalesced, L2)
    float ctT[EPW], ctU[EPW], cmT[EPW], cmU[EPW];
    #pragma unroll
    for (int j = 0; j < EPW; j++) {
        ctT[j] = g_ctop[ctop_off[j] + lane];
        ctU[j] = g_ctop[ctop_off[j] + lane + 32];
        cmT[j] = g_cmid[cmid_off[j] + lane];
        cmU[j] = g_cmid[cmid_off[j] + lane + 32];
    }

    // ---- Phase B: stage WbotP ----
    {
        const float4* src = (const float4*)g_WbotP;
        float4*       dst = (float4*)Wsh;
        #pragma unroll
        for (int i = 0; i < 2; i++) dst[i * 256 + tid] = src[i * 256 + tid];
    }
    __syncthreads();

    // ---- Phase C: 16 f-pair iters x 4 edges ----
    const ulonglong2* Wq = (const ulonglong2*)Wsh;
    const float* vb = vsh + (w * EPW) * CB;

    unsigned long long aT[EPW], aU[EPW];
    #pragma unroll
    for (int j = 0; j < EPW; j++) { aT[j] = 0ull; aU[j] = 0ull; }

    #pragma unroll
    for (int ip = 0; ip < NPB; ip++) {
        const ulonglong2 wq = Wq[ip * 32 + lane];
        #pragma unroll
        for (int j = 0; j < EPW; j++) {
            const unsigned long long vp =
                *(const unsigned long long*)(vb + j * CB + 2 * ip);  // broadcast
            FMA2(aT[j], vp, wq.x);
            FMA2(aU[j], vp, wq.y);
        }
    }

    // ---- Phase D: epilogue ----
    #pragma unroll
    for (int j = 0; j < EPW; j++) {
        float yT = __uint_as_float((unsigned)(aT[j] & 0xffffffffull))
                 + __uint_as_float((unsigned)(aT[j] >> 32))
                 + ctT[j] + cmT[j];
        float yU = __uint_as_float((unsigned)(aU[j] & 0xffffffffull))
                 + __uint_as_float((unsigned)(aU[j] >> 32))
                 + ctU[j] + cmU[j];
        yT = (yT > 0.0f) ? yT : NEG_SLOPE * yT;
        yU = (yU > 0.0f) ? yU : NEG_SLOPE * yU;

        float p = yT * waT + yU * waU;
        #pragma unroll
        for (int s = 16; s > 0; s >>= 1)
            p += __shfl_xor_sync(0xffffffffu, p, s);
        const float att = 1.0f / (1.0f + __expf(-(p + ba)));

        float* dst = out + cmid_off[j];   // (b*K + i2)*COUT
        atomicAdd(dst + lane,      att * yT);
        atomicAdd(dst + lane + 32, att * yU);
    }
}

// ---------------------------------------------------------------------------
extern "C" void kernel_launch(void* const* d_in, const int* in_sizes, int n_in,
                              void* d_out, int out_size)
{
    const float* sites1 = (const float*)d_in[0];
    const float* sites2 = (const float*)d_in[1];
    const float* bonds  = (const float*)d_in[2];
    const float* W_eq   = (const float*)d_in[3];
    const float* b_eq   = (const float*)d_in[4];
    const float* W_att  = (const float*)d_in[5];
    const float* b_att  = (const float*)d_in[6];
    // d_in[7] = idx2_oh (unused — collapsed analytically)
    const int*   idx1   = (const int*)d_in[8];
    const int*   idx2   = (const int*)d_in[9];
    // d_in[10], d_in[11] = perms1/perms2 (unused — permutations cancel)
    float* out = (float*)d_out;

    // prep: 64 CTAs x 256 threads
    {
        cudaLaunchConfig_t cfg = {};
        cfg.gridDim  = dim3(64);
        cfg.blockDim = dim3(256);
        cfg.stream = 0;
        cudaLaunchKernelEx(&cfg, prep_kernel, sites1, sites2, W_eq, b_eq, out);
    }

    // main with programmatic dependent launch (bonds-gather overlaps prep)
    {
        cudaLaunchConfig_t cfg = {};
        cfg.gridDim  = dim3(GRID_M);
        cfg.blockDim = dim3(256);
        cfg.stream = 0;
        cudaLaunchAttribute at[1];
        at[0].id = cudaLaunchAttributeProgrammaticStreamSerialization;
        at[0].val.programmaticStreamSerializationAllowed = 1;
        cfg.attrs = at;
        cfg.numAttrs = 1;
        cudaLaunchKernelEx(&cfg, main_kernel, bonds, W_att, b_att,
                           idx1, idx2, out);
    }
}